// round 6
// baseline (speedup 1.0000x reference)
#include <cuda_runtime.h>
#include <math.h>

#define BB  512
#define SSZ 16
#define HH  501
#define CC  7

#define BM 32
#define BN 32
#define BK 32
#define LDA 34      // BM+2 pad: keeps 8B alignment for float2 reads, kills store conflicts
#define NT 256

// Scratch (module-scope device globals; allocation-free per harness rules)
// g_hv slot i stores hv_{i-1}:  slot 0 = graph_state0 (z@W_lin1.T+b), slot idx+1 = hv_idx
__device__ float g_hv[(SSZ + 1) * BB * HH];
__device__ float g_hin[BB * HH];
__device__ float g_d1[(SSZ + 1) * BB];
__device__ float g_d2[(SSZ + 1) * BB];

__device__ __forceinline__ float sigf(float x) { return 1.0f / (1.0f + expf(-x)); }

// ---------------------------------------------------------------------------
// GEMM 1 (once): g_hv[slot0] = z @ W_lin1.T + b_lin1     (512x501 @ 501x501)
// ---------------------------------------------------------------------------
__global__ __launch_bounds__(NT) void k_lin1(const float* __restrict__ A,
                                             const float* __restrict__ W,
                                             const float* __restrict__ bias) {
    __shared__ float sA[BK][LDA];
    __shared__ float sW[BK][LDA];
    const int m0 = blockIdx.y * BM, n0 = blockIdx.x * BN;
    const int tid = threadIdx.x;
    const int tx = tid & 15, ty = tid >> 4;
    float a00 = 0.f, a01 = 0.f, a10 = 0.f, a11 = 0.f;

    for (int k0 = 0; k0 < HH; k0 += BK) {
#pragma unroll
        for (int i = 0; i < 4; i++) {
            int idx = tid + i * NT;
            int k = idx & 31, r = idx >> 5;
            int gk = k0 + k;
            sA[k][r] = (gk < HH) ? A[(m0 + r) * HH + gk] : 0.f;
            sW[k][r] = (gk < HH && (n0 + r) < HH) ? W[(n0 + r) * HH + gk] : 0.f;
        }
        __syncthreads();
#pragma unroll
        for (int kk = 0; kk < BK; kk++) {
            float2 av = *reinterpret_cast<const float2*>(&sA[kk][ty * 2]);
            float2 wv = *reinterpret_cast<const float2*>(&sW[kk][tx * 2]);
            a00 += av.x * wv.x; a01 += av.x * wv.y;
            a10 += av.y * wv.x; a11 += av.y * wv.y;
        }
        __syncthreads();
    }
    int m = m0 + ty * 2, n = n0 + tx * 2;
    if (n < HH) {
        g_hv[m * HH + n]       = a00 + bias[n];
        g_hv[(m + 1) * HH + n] = a10 + bias[n];
    }
    if (n + 1 < HH) {
        g_hv[m * HH + n + 1]       = a01 + bias[n + 1];
        g_hv[(m + 1) * HH + n + 1] = a11 + bias[n + 1];
    }
}

// ---------------------------------------------------------------------------
// GEMM 2 (per step, idx>=1): aggregation (gate+map fused)
//   a[b,:] = hv_{idx-1}[b,:] * dep[b, idx, idx-1]
//   g_hin  = 15*sig(bg)*bm + sig(a@Wg.T + bg) * (a@Wm.T + bm)
// ---------------------------------------------------------------------------
__global__ __launch_bounds__(NT) void k_agm(int step,
        const float* __restrict__ dep,
        const float* __restrict__ Wg, const float* __restrict__ bg,
        const float* __restrict__ Wm, const float* __restrict__ bm) {
    __shared__ float sA[BK][LDA];
    __shared__ float sG[BK][LDA];
    __shared__ float sM[BK][LDA];
    __shared__ float sMask[BM];
    const int m0 = blockIdx.y * BM, n0 = blockIdx.x * BN;
    const int tid = threadIdx.x;
    const int tx = tid & 15, ty = tid >> 4;
    const float* A = g_hv + step * BB * HH;   // hv_{step-1}

    if (tid < BM)
        sMask[tid] = dep[(m0 + tid) * SSZ * SSZ + step * SSZ + (step - 1)];
    __syncthreads();

    float g00=0.f,g01=0.f,g10=0.f,g11=0.f;
    float p00=0.f,p01=0.f,p10=0.f,p11=0.f;

    for (int k0 = 0; k0 < HH; k0 += BK) {
#pragma unroll
        for (int i = 0; i < 4; i++) {
            int idx = tid + i * NT;
            int k = idx & 31, r = idx >> 5;
            int gk = k0 + k;
            sA[k][r] = (gk < HH) ? A[(m0 + r) * HH + gk] * sMask[r] : 0.f;
            bool okn = (gk < HH) && ((n0 + r) < HH);
            sG[k][r] = okn ? Wg[(n0 + r) * HH + gk] : 0.f;
            sM[k][r] = okn ? Wm[(n0 + r) * HH + gk] : 0.f;
        }
        __syncthreads();
#pragma unroll
        for (int kk = 0; kk < BK; kk++) {
            float2 av = *reinterpret_cast<const float2*>(&sA[kk][ty * 2]);
            float2 gv = *reinterpret_cast<const float2*>(&sG[kk][tx * 2]);
            float2 mv = *reinterpret_cast<const float2*>(&sM[kk][tx * 2]);
            g00 += av.x * gv.x; g01 += av.x * gv.y;
            g10 += av.y * gv.x; g11 += av.y * gv.y;
            p00 += av.x * mv.x; p01 += av.x * mv.y;
            p10 += av.y * mv.x; p11 += av.y * mv.y;
        }
        __syncthreads();
    }
    int m = m0 + ty * 2, n = n0 + tx * 2;
#pragma unroll
    for (int in = 0; in < 2; in++) {
        int nn = n + in;
        if (nn >= HH) continue;
        float bgv = bg[nn], bmv = bm[nn];
        float base = 15.0f * sigf(bgv) * bmv;
        float u0 = (in ? g01 : g00) + bgv, v0 = (in ? p01 : p00) + bmv;
        float u1 = (in ? g11 : g10) + bgv, v1 = (in ? p11 : p10) + bmv;
        g_hin[m * HH + nn]       = base + sigf(u0) * v0;
        g_hin[(m + 1) * HH + nn] = base + sigf(u1) * v1;
    }
}

// ---------------------------------------------------------------------------
// GEMM 3 (per step): GRU cell, fused epilogue.
//   h = (use_hin ? g_hin : g_hv[slot0]);  gh = h @ W_hh.T + b_hh  (3 parts)
//   gi from one-hot-ish x (C=7, computed inline);  writes g_hv[slot step+1]
// ---------------------------------------------------------------------------
__global__ __launch_bounds__(NT) void k_gru(int step, int use_hin,
        const float* __restrict__ ne,
        const float* __restrict__ Wih, const float* __restrict__ bih,
        const float* __restrict__ Whh, const float* __restrict__ bhh) {
    __shared__ float sA[BK][LDA];
    __shared__ float sW[3][BK][LDA];
    const int m0 = blockIdx.y * BM, n0 = blockIdx.x * BN;
    const int tid = threadIdx.x;
    const int tx = tid & 15, ty = tid >> 4;
    const float* Hsrc = use_hin ? g_hin : g_hv;

    float acc[3][2][2];
#pragma unroll
    for (int p = 0; p < 3; p++)
#pragma unroll
        for (int i = 0; i < 2; i++)
#pragma unroll
            for (int j = 0; j < 2; j++) acc[p][i][j] = 0.f;

    for (int k0 = 0; k0 < HH; k0 += BK) {
#pragma unroll
        for (int i = 0; i < 4; i++) {
            int idx = tid + i * NT;
            int k = idx & 31, r = idx >> 5;
            int gk = k0 + k;
            sA[k][r] = (gk < HH) ? Hsrc[(m0 + r) * HH + gk] : 0.f;
            bool okn = (gk < HH) && ((n0 + r) < HH);
#pragma unroll
            for (int p = 0; p < 3; p++)
                sW[p][k][r] = okn ? Whh[(p * HH + n0 + r) * HH + gk] : 0.f;
        }
        __syncthreads();
#pragma unroll
        for (int kk = 0; kk < BK; kk++) {
            float2 av = *reinterpret_cast<const float2*>(&sA[kk][ty * 2]);
#pragma unroll
            for (int p = 0; p < 3; p++) {
                float2 wv = *reinterpret_cast<const float2*>(&sW[p][kk][tx * 2]);
                acc[p][0][0] += av.x * wv.x; acc[p][0][1] += av.x * wv.y;
                acc[p][1][0] += av.y * wv.x; acc[p][1][1] += av.y * wv.y;
            }
        }
        __syncthreads();
    }

    float* O = g_hv + (step + 1) * BB * HH;
#pragma unroll
    for (int im = 0; im < 2; im++) {
        int b = m0 + ty * 2 + im;
        float x[CC];
#pragma unroll
        for (int c = 0; c < CC; c++) x[c] = ne[b * SSZ * CC + step * CC + c];
#pragma unroll
        for (int in = 0; in < 2; in++) {
            int n = n0 + tx * 2 + in;
            if (n >= HH) continue;
            float gir = bih[n], giz = bih[HH + n], gin = bih[2 * HH + n];
#pragma unroll
            for (int c = 0; c < CC; c++) {
                gir += x[c] * Wih[n * CC + c];
                giz += x[c] * Wih[(HH + n) * CC + c];
                gin += x[c] * Wih[(2 * HH + n) * CC + c];
            }
            float ghr = acc[0][im][in] + bhh[n];
            float ghz = acc[1][im][in] + bhh[HH + n];
            float ghn = acc[2][im][in] + bhh[2 * HH + n];
            float r  = sigf(gir + ghr);
            float zg = sigf(giz + ghz);
            float nv = tanhf(gin + r * ghn);
            float hp = Hsrc[b * HH + n];
            O[b * HH + n] = (1.f - zg) * nv + zg * hp;
        }
    }
}

// ---------------------------------------------------------------------------
// Post: edge-logit dot products  d1[i]=w1.hv_i  d2[i]=w2.hv_i  (warp per row)
// ---------------------------------------------------------------------------
__global__ __launch_bounds__(256) void k_dots(const float* __restrict__ We) {
    int warp = threadIdx.x >> 5, lane = threadIdx.x & 31;
    int row = blockIdx.x * 8 + warp;             // < (S+1)*B, exact grid
    const float* hv = g_hv + row * HH;
    float a1 = 0.f, a2 = 0.f;
    for (int h = lane; h < HH; h += 32) {
        float v = hv[h];
        a1 += v * We[h];
        a2 += v * We[HH + h];
    }
#pragma unroll
    for (int o = 16; o; o >>= 1) {
        a1 += __shfl_xor_sync(0xffffffffu, a1, o);
        a2 += __shfl_xor_sync(0xffffffffu, a2, o);
    }
    if (lane == 0) { g_d1[row] = a1; g_d2[row] = a2; }
}

// ---------------------------------------------------------------------------
// Post: generated dep graph.
//   edges[b,idx,idx-1]: logit = d1[slot idx] + d2[slot idx] + be   (hv_{idx-1}, hv_{idx-1})
//   edges[b,idx,j<idx-1]: logit = d1[slot idx+1] + d2[slot j+1] + be (hv_idx, hv_j)
//   sigmoid(x) >= 0.5  <=>  x >= 0
// ---------------------------------------------------------------------------
__global__ void k_edges(const float* __restrict__ be_p, float* __restrict__ out) {
    int gid = blockIdx.x * blockDim.x + threadIdx.x;   // b*256 + idx*16 + j
    int j = gid & 15, idx = (gid >> 4) & 15, b = gid >> 8;
    float val = 0.f;
    if (idx > 0 && j < idx) {
        float t;
        if (j == idx - 1) t = g_d1[idx * BB + b] + g_d2[idx * BB + b];
        else              t = g_d1[(idx + 1) * BB + b] + g_d2[(j + 1) * BB + b];
        t += be_p[0];
        val = (t >= 0.f) ? 1.f : 0.f;
    }
    out[gid] = val;
}

// ---------------------------------------------------------------------------
// Post: node encodings.  enc[b,idx,:] = softmax(hv_{idx-1} @ W_vert.T + b_vert)
// Warp per (b,idx) row.
// ---------------------------------------------------------------------------
__global__ __launch_bounds__(256) void k_enc(const float* __restrict__ Wv,
                                             const float* __restrict__ bv,
                                             float* __restrict__ out2) {
    int warp = threadIdx.x >> 5, lane = threadIdx.x & 31;
    int row = blockIdx.x * 8 + warp;       // b*S + idx, exact grid
    int b = row >> 4, idx = row & 15;
    const float* hv = g_hv + (idx * BB + b) * HH;   // slot idx = hv_{idx-1}
    float l[CC];
#pragma unroll
    for (int c = 0; c < CC; c++) l[c] = 0.f;
    for (int h = lane; h < HH; h += 32) {
        float v = hv[h];
#pragma unroll
        for (int c = 0; c < CC; c++) l[c] += v * Wv[c * HH + h];
    }
#pragma unroll
    for (int c = 0; c < CC; c++)
#pragma unroll
        for (int o = 16; o; o >>= 1) l[c] += __shfl_xor_sync(0xffffffffu, l[c], o);
    if (lane == 0) {
        float mx = -1e30f;
#pragma unroll
        for (int c = 0; c < CC; c++) { l[c] += bv[c]; mx = fmaxf(mx, l[c]); }
        float s = 0.f;
#pragma unroll
        for (int c = 0; c < CC; c++) { l[c] = expf(l[c] - mx); s += l[c]; }
        float inv = 1.f / s;
#pragma unroll
        for (int c = 0; c < CC; c++) out2[row * CC + c] = l[c] * inv;
    }
}

// ---------------------------------------------------------------------------
extern "C" void kernel_launch(void* const* d_in, const int* in_sizes, int n_in,
                              void* d_out, int out_size) {
    const float* z      = (const float*)d_in[0];
    const float* dep    = (const float*)d_in[1];
    const float* ne     = (const float*)d_in[2];
    const float* W_lin1 = (const float*)d_in[3];
    const float* b_lin1 = (const float*)d_in[4];
    const float* W_vert = (const float*)d_in[5];
    const float* b_vert = (const float*)d_in[6];
    const float* W_edge = (const float*)d_in[7];
    const float* b_edge = (const float*)d_in[8];
    const float* W_gate = (const float*)d_in[9];
    const float* b_gate = (const float*)d_in[10];
    const float* W_map  = (const float*)d_in[11];
    const float* b_map  = (const float*)d_in[12];
    const float* W_ih   = (const float*)d_in[13];
    const float* b_ih   = (const float*)d_in[14];
    const float* W_hh   = (const float*)d_in[15];
    const float* b_hh   = (const float*)d_in[16];
    float* out = (float*)d_out;

    dim3 gg((HH + BN - 1) / BN, BB / BM);   // (16, 16)

    k_lin1<<<gg, NT>>>(z, W_lin1, b_lin1);                      // slot 0 = graph_state0
    k_gru<<<gg, NT>>>(0, 0, ne, W_ih, b_ih, W_hh, b_hh);        // hv_0 (h = graph_state0)
    for (int step = 1; step < SSZ; step++) {
        k_agm<<<gg, NT>>>(step, dep, W_gate, b_gate, W_map, b_map);
        k_gru<<<gg, NT>>>(step, 1, ne, W_ih, b_ih, W_hh, b_hh);
    }
    k_dots<<<(SSZ + 1) * BB / 8, 256>>>(W_edge);
    k_edges<<<BB * SSZ * SSZ / 256, 256>>>(b_edge, out);
    k_enc<<<BB * SSZ / 8, 256>>>(W_vert, b_vert, out + BB * SSZ * SSZ);
}

// round 9
// speedup vs baseline: 1.2774x; 1.2774x over previous
#include <cuda_runtime.h>
#include <math.h>

#define BB  512
#define SSZ 16
#define HH  501
#define CC  7

#define BM 64
#define BN 32
#define BK 32
#define NT 128
#define NKT 16          // ceil(501/32)
#define LDA_ 68         // BM+4 pad (16B-aligned stride, float4 reads)
#define LDW_ 36         // BN+4 pad

// Scratch (module-scope device globals; allocation-free per harness rules)
// g_hv slot i stores hv_{i-1}: slot 0 = graph_state0, slot idx+1 = hv_idx
__device__ float g_hv[(SSZ + 1) * BB * HH];
__device__ float g_hin[BB * HH];
__device__ float g_d1[(SSZ + 1) * BB];
__device__ float g_d2[(SSZ + 1) * BB];

typedef unsigned long long u64;

__device__ __forceinline__ float sigf(float x) { return 1.0f / (1.0f + expf(-x)); }
__device__ __forceinline__ u64 pk2(float x, float y) {
    u64 r; asm("mov.b64 %0,{%1,%2};" : "=l"(r) : "f"(x), "f"(y)); return r;
}
__device__ __forceinline__ void fma2(u64& d, u64 a, u64 b) {
    asm("fma.rn.f32x2 %0,%1,%2,%0;" : "+l"(d) : "l"(a), "l"(b));
}
__device__ __forceinline__ void up2(u64 v, float& a, float& b) {
    asm("mov.b64 {%0,%1},%2;" : "=f"(a), "=f"(b) : "l"(v));
}

// ===========================================================================
// k_gru: gh = Hsrc @ W_hh.T (3 parts fused) ; epilogue = full GRU cell.
// BM=64 x BN=32 tile, 128 thr, 4x4 microtile, double-buffered, FFMA2.
// ===========================================================================
__global__ __launch_bounds__(NT) void k_gru(int step, int use_hin,
        const float* __restrict__ ne,
        const float* __restrict__ Wih, const float* __restrict__ bih,
        const float* __restrict__ Whh, const float* __restrict__ bhh) {
    __shared__ __align__(16) float sA[2][BK][LDA_];
    __shared__ __align__(16) float sW[2][3][BK][LDW_];
    const int m0 = blockIdx.y * BM, n0 = blockIdx.x * BN;
    const int tid = threadIdx.x;
    const int tx = tid & 7, ty = tid >> 3;
    const int n4 = tx * 4, m4 = ty * 4;
    const int kz = tid & 31, r0 = tid >> 5;     // load lane mapping
    const float* Hsrc = use_hin ? g_hin : g_hv;

    u64 acc[3][4][2];
#pragma unroll
    for (int p = 0; p < 3; p++)
#pragma unroll
        for (int i = 0; i < 4; i++) { acc[p][i][0] = 0ull; acc[p][i][1] = 0ull; }

    float rAv[16], rWv[3][8];

    // ---- prefetch + store tile 0 ----
#pragma unroll
    for (int i = 0; i < 16; i++)
        rAv[i] = Hsrc[(m0 + r0 + 4 * i) * HH + kz];
#pragma unroll
    for (int j = 0; j < 8; j++) {
        int r = r0 + 4 * j;
        bool ok = (n0 + r) < HH;
#pragma unroll
        for (int p = 0; p < 3; p++)
            rWv[p][j] = ok ? Whh[(p * HH + n0 + r) * HH + kz] : 0.f;
    }
#pragma unroll
    for (int i = 0; i < 16; i++) sA[0][kz][r0 + 4 * i] = rAv[i];
#pragma unroll
    for (int j = 0; j < 8; j++)
#pragma unroll
        for (int p = 0; p < 3; p++) sW[0][p][kz][r0 + 4 * j] = rWv[p][j];
    __syncthreads();

    for (int t = 0; t < NKT; t++) {
        int cur = t & 1;
        if (t + 1 < NKT) {
            int gk = (t + 1) * BK + kz;
            bool okk = gk < HH;
#pragma unroll
            for (int i = 0; i < 16; i++)
                rAv[i] = okk ? Hsrc[(m0 + r0 + 4 * i) * HH + gk] : 0.f;
#pragma unroll
            for (int j = 0; j < 8; j++) {
                int r = r0 + 4 * j;
                bool ok = okk && ((n0 + r) < HH);
#pragma unroll
                for (int p = 0; p < 3; p++)
                    rWv[p][j] = ok ? Whh[(p * HH + n0 + r) * HH + gk] : 0.f;
            }
        }
#pragma unroll
        for (int kk = 0; kk < BK; kk++) {
            float4 av = *reinterpret_cast<const float4*>(&sA[cur][kk][m4]);
            u64 aa[4] = { pk2(av.x, av.x), pk2(av.y, av.y),
                          pk2(av.z, av.z), pk2(av.w, av.w) };
#pragma unroll
            for (int p = 0; p < 3; p++) {
                ulonglong2 wv = *reinterpret_cast<const ulonglong2*>(&sW[cur][p][kk][n4]);
#pragma unroll
                for (int im = 0; im < 4; im++) {
                    fma2(acc[p][im][0], aa[im], wv.x);
                    fma2(acc[p][im][1], aa[im], wv.y);
                }
            }
        }
        if (t + 1 < NKT) {
            int nb = (t + 1) & 1;
#pragma unroll
            for (int i = 0; i < 16; i++) sA[nb][kz][r0 + 4 * i] = rAv[i];
#pragma unroll
            for (int j = 0; j < 8; j++)
#pragma unroll
                for (int p = 0; p < 3; p++) sW[nb][p][kz][r0 + 4 * j] = rWv[p][j];
            __syncthreads();
        }
    }

    // ---- epilogue: GRU cell ----
    float af[3][4][4];
#pragma unroll
    for (int p = 0; p < 3; p++)
#pragma unroll
        for (int im = 0; im < 4; im++) {
            up2(acc[p][im][0], af[p][im][0], af[p][im][1]);
            up2(acc[p][im][1], af[p][im][2], af[p][im][3]);
        }
    float* O = g_hv + (step + 1) * BB * HH;
#pragma unroll
    for (int im = 0; im < 4; im++) {
        int b = m0 + m4 + im;
        float x[CC];
#pragma unroll
        for (int c = 0; c < CC; c++) x[c] = ne[b * SSZ * CC + step * CC + c];
#pragma unroll
        for (int jn = 0; jn < 4; jn++) {
            int n = n0 + n4 + jn;
            if (n >= HH) continue;
            float gir = bih[n], giz = bih[HH + n], gin = bih[2 * HH + n];
#pragma unroll
            for (int c = 0; c < CC; c++) {
                gir += x[c] * Wih[n * CC + c];
                giz += x[c] * Wih[(HH + n) * CC + c];
                gin += x[c] * Wih[(2 * HH + n) * CC + c];
            }
            float ghr = af[0][im][jn] + bhh[n];
            float ghz = af[1][im][jn] + bhh[HH + n];
            float ghn = af[2][im][jn] + bhh[2 * HH + n];
            float r  = sigf(gir + ghr);
            float zg = sigf(giz + ghz);
            float nv = tanhf(gin + r * ghn);
            float hp = Hsrc[b * HH + n];
            O[b * HH + n] = (1.f - zg) * nv + zg * hp;
        }
    }
}

// ===========================================================================
// k_agm: masked aggregation, gate+map fused (P=2).
//   a[b,:] = hv_{step-1}[b,:] * dep[b,step,step-1]
//   g_hin  = 15*sig(bg)*bm + sig(a@Wg.T+bg) * (a@Wm.T+bm)
// ===========================================================================
__global__ __launch_bounds__(NT) void k_agm(int step,
        const float* __restrict__ dep,
        const float* __restrict__ Wg, const float* __restrict__ bg,
        const float* __restrict__ Wm, const float* __restrict__ bm) {
    __shared__ __align__(16) float sA[2][BK][LDA_];
    __shared__ __align__(16) float sW[2][2][BK][LDW_];
    const int m0 = blockIdx.y * BM, n0 = blockIdx.x * BN;
    const int tid = threadIdx.x;
    const int tx = tid & 7, ty = tid >> 3;
    const int n4 = tx * 4, m4 = ty * 4;
    const int kz = tid & 31, r0 = tid >> 5;
    const float* A = g_hv + step * BB * HH;     // hv_{step-1}

    float rMask[16];
#pragma unroll
    for (int i = 0; i < 16; i++)
        rMask[i] = dep[(m0 + r0 + 4 * i) * SSZ * SSZ + step * SSZ + (step - 1)];

    u64 acc[2][4][2];
#pragma unroll
    for (int p = 0; p < 2; p++)
#pragma unroll
        for (int i = 0; i < 4; i++) { acc[p][i][0] = 0ull; acc[p][i][1] = 0ull; }

    float rAv[16], rWv[2][8];

#pragma unroll
    for (int i = 0; i < 16; i++)
        rAv[i] = A[(m0 + r0 + 4 * i) * HH + kz] * rMask[i];
#pragma unroll
    for (int j = 0; j < 8; j++) {
        int r = r0 + 4 * j;
        bool ok = (n0 + r) < HH;
        rWv[0][j] = ok ? Wg[(n0 + r) * HH + kz] : 0.f;
        rWv[1][j] = ok ? Wm[(n0 + r) * HH + kz] : 0.f;
    }
#pragma unroll
    for (int i = 0; i < 16; i++) sA[0][kz][r0 + 4 * i] = rAv[i];
#pragma unroll
    for (int j = 0; j < 8; j++) {
        sW[0][0][kz][r0 + 4 * j] = rWv[0][j];
        sW[0][1][kz][r0 + 4 * j] = rWv[1][j];
    }
    __syncthreads();

    for (int t = 0; t < NKT; t++) {
        int cur = t & 1;
        if (t + 1 < NKT) {
            int gk = (t + 1) * BK + kz;
            bool okk = gk < HH;
#pragma unroll
            for (int i = 0; i < 16; i++)
                rAv[i] = okk ? A[(m0 + r0 + 4 * i) * HH + gk] * rMask[i] : 0.f;
#pragma unroll
            for (int j = 0; j < 8; j++) {
                int r = r0 + 4 * j;
                bool ok = okk && ((n0 + r) < HH);
                rWv[0][j] = ok ? Wg[(n0 + r) * HH + gk] : 0.f;
                rWv[1][j] = ok ? Wm[(n0 + r) * HH + gk] : 0.f;
            }
        }
#pragma unroll
        for (int kk = 0; kk < BK; kk++) {
            float4 av = *reinterpret_cast<const float4*>(&sA[cur][kk][m4]);
            u64 aa[4] = { pk2(av.x, av.x), pk2(av.y, av.y),
                          pk2(av.z, av.z), pk2(av.w, av.w) };
#pragma unroll
            for (int p = 0; p < 2; p++) {
                ulonglong2 wv = *reinterpret_cast<const ulonglong2*>(&sW[cur][p][kk][n4]);
#pragma unroll
                for (int im = 0; im < 4; im++) {
                    fma2(acc[p][im][0], aa[im], wv.x);
                    fma2(acc[p][im][1], aa[im], wv.y);
                }
            }
        }
        if (t + 1 < NKT) {
            int nb = (t + 1) & 1;
#pragma unroll
            for (int i = 0; i < 16; i++) sA[nb][kz][r0 + 4 * i] = rAv[i];
#pragma unroll
            for (int j = 0; j < 8; j++) {
                sW[nb][0][kz][r0 + 4 * j] = rWv[0][j];
                sW[nb][1][kz][r0 + 4 * j] = rWv[1][j];
            }
            __syncthreads();
        }
    }

    float af[2][4][4];
#pragma unroll
    for (int p = 0; p < 2; p++)
#pragma unroll
        for (int im = 0; im < 4; im++) {
            up2(acc[p][im][0], af[p][im][0], af[p][im][1]);
            up2(acc[p][im][1], af[p][im][2], af[p][im][3]);
        }
#pragma unroll
    for (int jn = 0; jn < 4; jn++) {
        int n = n0 + n4 + jn;
        if (n >= HH) continue;
        float bgv = bg[n], bmv = bm[n];
        float base = 15.0f * sigf(bgv) * bmv;
#pragma unroll
        for (int im = 0; im < 4; im++) {
            int b = m0 + m4 + im;
            float u = af[0][im][jn] + bgv;
            float v = af[1][im][jn] + bmv;
            g_hin[b * HH + n] = base + sigf(u) * v;
        }
    }
}

// ===========================================================================
// k_lin1 (once): g_hv[slot0] = z @ W_lin1.T + b_lin1
// ===========================================================================
__global__ __launch_bounds__(NT) void k_lin1(const float* __restrict__ A,
                                             const float* __restrict__ W,
                                             const float* __restrict__ bias) {
    __shared__ __align__(16) float sA[2][BK][LDA_];
    __shared__ __align__(16) float sW[2][BK][LDW_];
    const int m0 = blockIdx.y * BM, n0 = blockIdx.x * BN;
    const int tid = threadIdx.x;
    const int tx = tid & 7, ty = tid >> 3;
    const int n4 = tx * 4, m4 = ty * 4;
    const int kz = tid & 31, r0 = tid >> 5;

    u64 acc[4][2];
#pragma unroll
    for (int i = 0; i < 4; i++) { acc[i][0] = 0ull; acc[i][1] = 0ull; }

    float rAv[16], rWv[8];
#pragma unroll
    for (int i = 0; i < 16; i++)
        rAv[i] = A[(m0 + r0 + 4 * i) * HH + kz];
#pragma unroll
    for (int j = 0; j < 8; j++) {
        int r = r0 + 4 * j;
        rWv[j] = ((n0 + r) < HH) ? W[(n0 + r) * HH + kz] : 0.f;
    }
#pragma unroll
    for (int i = 0; i < 16; i++) sA[0][kz][r0 + 4 * i] = rAv[i];
#pragma unroll
    for (int j = 0; j < 8; j++) sW[0][kz][r0 + 4 * j] = rWv[j];
    __syncthreads();

    for (int t = 0; t < NKT; t++) {
        int cur = t & 1;
        if (t + 1 < NKT) {
            int gk = (t + 1) * BK + kz;
            bool okk = gk < HH;
#pragma unroll
            for (int i = 0; i < 16; i++)
                rAv[i] = okk ? A[(m0 + r0 + 4 * i) * HH + gk] : 0.f;
#pragma unroll
            for (int j = 0; j < 8; j++) {
                int r = r0 + 4 * j;
                rWv[j] = (okk && ((n0 + r) < HH)) ? W[(n0 + r) * HH + gk] : 0.f;
            }
        }
#pragma unroll
        for (int kk = 0; kk < BK; kk++) {
            float4 av = *reinterpret_cast<const float4*>(&sA[cur][kk][m4]);
            u64 aa[4] = { pk2(av.x, av.x), pk2(av.y, av.y),
                          pk2(av.z, av.z), pk2(av.w, av.w) };
            ulonglong2 wv = *reinterpret_cast<const ulonglong2*>(&sW[cur][kk][n4]);
#pragma unroll
            for (int im = 0; im < 4; im++) {
                fma2(acc[im][0], aa[im], wv.x);
                fma2(acc[im][1], aa[im], wv.y);
            }
        }
        if (t + 1 < NKT) {
            int nb = (t + 1) & 1;
#pragma unroll
            for (int i = 0; i < 16; i++) sA[nb][kz][r0 + 4 * i] = rAv[i];
#pragma unroll
            for (int j = 0; j < 8; j++) sW[nb][kz][r0 + 4 * j] = rWv[j];
            __syncthreads();
        }
    }

#pragma unroll
    for (int im = 0; im < 4; im++) {
        float v0, v1, v2, v3;
        up2(acc[im][0], v0, v1);
        up2(acc[im][1], v2, v3);
        int b = m0 + m4 + im;
        float vv[4] = { v0, v1, v2, v3 };
#pragma unroll
        for (int jn = 0; jn < 4; jn++) {
            int n = n0 + n4 + jn;
            if (n < HH) g_hv[b * HH + n] = vv[jn] + bias[n];
        }
    }
}

// ---------------------------------------------------------------------------
// Post: edge-logit dot products  d1[i]=w1.hv_i  d2[i]=w2.hv_i  (warp per row)
// ---------------------------------------------------------------------------
__global__ __launch_bounds__(256) void k_dots(const float* __restrict__ We) {
    int warp = threadIdx.x >> 5, lane = threadIdx.x & 31;
    int row = blockIdx.x * 8 + warp;             // < (S+1)*B, exact grid
    const float* hv = g_hv + row * HH;
    float a1 = 0.f, a2 = 0.f;
    for (int h = lane; h < HH; h += 32) {
        float v = hv[h];
        a1 += v * We[h];
        a2 += v * We[HH + h];
    }
#pragma unroll
    for (int o = 16; o; o >>= 1) {
        a1 += __shfl_xor_sync(0xffffffffu, a1, o);
        a2 += __shfl_xor_sync(0xffffffffu, a2, o);
    }
    if (lane == 0) { g_d1[row] = a1; g_d2[row] = a2; }
}

// ---------------------------------------------------------------------------
// Post: generated dep graph (hard threshold sigmoid(x)>=0.5 <=> x>=0)
// ---------------------------------------------------------------------------
__global__ void k_edges(const float* __restrict__ be_p, float* __restrict__ out) {
    int gid = blockIdx.x * blockDim.x + threadIdx.x;   // b*256 + idx*16 + j
    int j = gid & 15, idx = (gid >> 4) & 15, b = gid >> 8;
    float val = 0.f;
    if (idx > 0 && j < idx) {
        float t;
        if (j == idx - 1) t = g_d1[idx * BB + b] + g_d2[idx * BB + b];
        else              t = g_d1[(idx + 1) * BB + b] + g_d2[(j + 1) * BB + b];
        t += be_p[0];
        val = (t >= 0.f) ? 1.f : 0.f;
    }
    out[gid] = val;
}

// ---------------------------------------------------------------------------
// Post: node encodings.  enc[b,idx,:] = softmax(hv_{idx-1} @ W_vert.T + b_vert)
// ---------------------------------------------------------------------------
__global__ __launch_bounds__(256) void k_enc(const float* __restrict__ Wv,
                                             const float* __restrict__ bv,
                                             float* __restrict__ out2) {
    int warp = threadIdx.x >> 5, lane = threadIdx.x & 31;
    int row = blockIdx.x * 8 + warp;       // b*S + idx, exact grid
    int b = row >> 4, idx = row & 15;
    const float* hv = g_hv + (idx * BB + b) * HH;   // slot idx = hv_{idx-1}
    float l[CC];
#pragma unroll
    for (int c = 0; c < CC; c++) l[c] = 0.f;
    for (int h = lane; h < HH; h += 32) {
        float v = hv[h];
#pragma unroll
        for (int c = 0; c < CC; c++) l[c] += v * Wv[c * HH + h];
    }
#pragma unroll
    for (int c = 0; c < CC; c++)
#pragma unroll
        for (int o = 16; o; o >>= 1) l[c] += __shfl_xor_sync(0xffffffffu, l[c], o);
    if (lane == 0) {
        float mx = -1e30f;
#pragma unroll
        for (int c = 0; c < CC; c++) { l[c] += bv[c]; mx = fmaxf(mx, l[c]); }
        float s = 0.f;
#pragma unroll
        for (int c = 0; c < CC; c++) { l[c] = expf(l[c] - mx); s += l[c]; }
        float inv = 1.f / s;
#pragma unroll
        for (int c = 0; c < CC; c++) out2[row * CC + c] = l[c] * inv;
    }
}

// ---------------------------------------------------------------------------
extern "C" void kernel_launch(void* const* d_in, const int* in_sizes, int n_in,
                              void* d_out, int out_size) {
    const float* z      = (const float*)d_in[0];
    const float* dep    = (const float*)d_in[1];
    const float* ne     = (const float*)d_in[2];
    const float* W_lin1 = (const float*)d_in[3];
    const float* b_lin1 = (const float*)d_in[4];
    const float* W_vert = (const float*)d_in[5];
    const float* b_vert = (const float*)d_in[6];
    const float* W_edge = (const float*)d_in[7];
    const float* b_edge = (const float*)d_in[8];
    const float* W_gate = (const float*)d_in[9];
    const float* b_gate = (const float*)d_in[10];
    const float* W_map  = (const float*)d_in[11];
    const float* b_map  = (const float*)d_in[12];
    const float* W_ih   = (const float*)d_in[13];
    const float* b_ih   = (const float*)d_in[14];
    const float* W_hh   = (const float*)d_in[15];
    const float* b_hh   = (const float*)d_in[16];
    float* out = (float*)d_out;

    dim3 gg((HH + BN - 1) / BN, BB / BM);   // (16, 8) = 128 CTAs = one wave

    k_lin1<<<gg, NT>>>(z, W_lin1, b_lin1);                      // slot 0
    k_gru<<<gg, NT>>>(0, 0, ne, W_ih, b_ih, W_hh, b_hh);        // hv_0
    for (int step = 1; step < SSZ; step++) {
        k_agm<<<gg, NT>>>(step, dep, W_gate, b_gate, W_map, b_map);
        k_gru<<<gg, NT>>>(step, 1, ne, W_ih, b_ih, W_hh, b_hh);
    }
    k_dots<<<(SSZ + 1) * BB / 8, 256>>>(W_edge);
    k_edges<<<BB * SSZ * SSZ / 256, 256>>>(b_edge, out);
    k_enc<<<BB * SSZ / 8, 256>>>(W_vert, b_vert, out + BB * SSZ * SSZ);
}